// round 1
// baseline (speedup 1.0000x reference)
#include <cuda_runtime.h>
#include <math.h>

#define T_STEPS 512
#define BATCH   256
#define IN_DIM  256
#define HID     1024
#define NCTAS   128
#define SROW    36   // padded smem row (floats): bank-conflict-free & float4-aligned

// 128 CTAs x 128x128 fp32 partial tiles (8 MB), plus barrier state.
__device__ float    g_partial[NCTAS * 128 * 128];
__device__ unsigned g_bar_count;
__device__ unsigned g_bar_phase;

__device__ __forceinline__ unsigned f2tf(float f) {
    unsigned u;
    asm("cvt.rna.tf32.f32 %0, %1;" : "=r"(u) : "f"(f));
    return u;
}

__device__ __forceinline__ void mma8(float c[4], const unsigned a[4], const unsigned b[2]) {
    asm volatile(
        "mma.sync.aligned.m16n8k8.row.col.f32.tf32.tf32.f32 "
        "{%0,%1,%2,%3}, {%4,%5,%6,%7}, {%8,%9}, {%0,%1,%2,%3};\n"
        : "+f"(c[0]), "+f"(c[1]), "+f"(c[2]), "+f"(c[3])
        : "r"(a[0]), "r"(a[1]), "r"(a[2]), "r"(a[3]), "r"(b[0]), "r"(b[1]));
}

// Load a 128-row x 32-col fp32 tile -> smem as tf32 bits. 256 threads.
__device__ __forceinline__ void load_tile(const float* __restrict__ g, int ld,
                                          int row0, int col0, unsigned* s) {
    int f = threadIdx.x;
    #pragma unroll
    for (int it = 0; it < 4; it++, f += 256) {
        int r  = f >> 3;
        int c4 = (f & 7) << 2;
        const float4 v = *reinterpret_cast<const float4*>(
            g + (size_t)(row0 + r) * ld + col0 + c4);
        uint4 w;
        w.x = f2tf(v.x); w.y = f2tf(v.y); w.z = f2tf(v.z); w.w = f2tf(v.w);
        *reinterpret_cast<uint4*>(s + r * SROW + c4) = w;
    }
}

// One 32-deep K block of warp-level MMAs on the CTA's 128x128 tile.
__device__ __forceinline__ void mma_block(float c[4][4][4],
                                          const unsigned* As, const unsigned* Bs,
                                          int wm, int wn, int g, int tig) {
    #pragma unroll
    for (int ks = 0; ks < 4; ks++) {
        const int k8 = ks * 8;
        unsigned a[4][4], b[4][2];
        #pragma unroll
        for (int mi = 0; mi < 4; mi++) {
            const unsigned* p = As + (wm * 64 + mi * 16 + g) * SROW + k8 + tig;
            a[mi][0] = p[0];
            a[mi][1] = p[8 * SROW];
            a[mi][2] = p[4];
            a[mi][3] = p[8 * SROW + 4];
        }
        #pragma unroll
        for (int ni = 0; ni < 4; ni++) {
            const unsigned* p = Bs + (wn * 32 + ni * 8 + g) * SROW + k8 + tig;
            b[ni][0] = p[0];
            b[ni][1] = p[4];
        }
        #pragma unroll
        for (int mi = 0; mi < 4; mi++)
            #pragma unroll
            for (int ni = 0; ni < 4; ni++)
                mma8(c[mi][ni], a[mi], b[ni]);
    }
}

// ---------------------------------------------------------------------------
// Kernel 1: Xpre = input @ Wih^T + bias, written straight into d_out[t,b,:].
// M = T*B = 131072 (blockIdx.y tiles of 128), N = 1024 (blockIdx.x tiles of 128), K = 256.
// ---------------------------------------------------------------------------
__global__ void __launch_bounds__(256, 1)
precompute_kernel(const float* __restrict__ input, const float* __restrict__ Wih,
                  const float* __restrict__ bias, float* __restrict__ out) {
    __shared__ unsigned As[128 * SROW];
    __shared__ unsigned Bs[128 * SROW];

    const int m0 = blockIdx.y * 128;
    const int n0 = blockIdx.x * 128;
    const int warp = threadIdx.x >> 5, lane = threadIdx.x & 31;
    const int wm = warp >> 2, wn = warp & 3, g = lane >> 2, tig = lane & 3;

    float c[4][4][4];
    #pragma unroll
    for (int i = 0; i < 4; i++)
        #pragma unroll
        for (int j = 0; j < 4; j++)
            #pragma unroll
            for (int k = 0; k < 4; k++) c[i][j][k] = 0.f;

    for (int kc = 0; kc < IN_DIM; kc += 32) {
        load_tile(input, IN_DIM, m0, kc, As);
        load_tile(Wih,   IN_DIM, n0, kc, Bs);
        __syncthreads();
        mma_block(c, As, Bs, wm, wn, g, tig);
        __syncthreads();
    }

    #pragma unroll
    for (int mi = 0; mi < 4; mi++) {
        const int row = m0 + wm * 64 + mi * 16 + g;
        #pragma unroll
        for (int ni = 0; ni < 4; ni++) {
            const int col = n0 + wn * 32 + ni * 8 + 2 * tig;
            const float b0 = bias[col], b1 = bias[col + 1];
            float2 v0 = make_float2(c[mi][ni][0] + b0, c[mi][ni][1] + b1);
            float2 v1 = make_float2(c[mi][ni][2] + b0, c[mi][ni][3] + b1);
            *reinterpret_cast<float2*>(out + (size_t)row * HID + col)       = v0;
            *reinterpret_cast<float2*>(out + (size_t)(row + 8) * HID + col) = v1;
        }
    }
}

// ---------------------------------------------------------------------------
// Persistent recurrence kernel: 128 co-resident CTAs, 512 timesteps.
// Phase A: split-K (8-way) GEMM partials of h @ Whh^T into g_partial.
// Phase B: reduce 8 partials + Xpre (in d_out[t]) -> tanh -> EMA -> d_out[t].
// Two atomic grid barriers per step.
// ---------------------------------------------------------------------------
__device__ __forceinline__ void grid_barrier() {
    __threadfence();
    __syncthreads();
    if (threadIdx.x == 0) {
        const unsigned phase = *(volatile unsigned*)&g_bar_phase;
        if (atomicAdd(&g_bar_count, 1u) == NCTAS - 1) {
            *(volatile unsigned*)&g_bar_count = 0u;
            __threadfence();
            atomicAdd(&g_bar_phase, 1u);
        } else {
            while (*(volatile unsigned*)&g_bar_phase == phase) __nanosleep(64);
        }
        __threadfence();
    }
    __syncthreads();
}

__global__ void __launch_bounds__(256, 1)
recurrence_kernel(const float* __restrict__ h0, const float* __restrict__ Whh,
                  float* __restrict__ out, int write_tail) {
    __shared__ unsigned As[128 * SROW];
    __shared__ unsigned Bs[128 * SROW];

    const int cta  = blockIdx.x;       // 0..127
    const int tile = cta >> 3;         // 0..15  (output tile)
    const int sub  = cta & 7;          // 0..7   (K split)
    const int mt   = tile >> 3;        // 0..1
    const int nt   = tile & 7;         // 0..7
    const int m0   = mt * 128;
    const int n0   = nt * 128;
    const int kc0  = sub * 128;

    const int warp = threadIdx.x >> 5, lane = threadIdx.x & 31;
    const int wm = warp >> 2, wn = warp & 3, g = lane >> 2, tig = lane & 3;

    float* myPart = g_partial + (size_t)cta * (128 * 128);

    for (int t = 0; t < T_STEPS; t++) {
        const float* h = (t == 0) ? h0 : out + (size_t)(t - 1) * BATCH * HID;

        // ---- Phase A: partial GEMM (128x128 tile, K chunk 128) ----
        float c[4][4][4];
        #pragma unroll
        for (int i = 0; i < 4; i++)
            #pragma unroll
            for (int j = 0; j < 4; j++)
                #pragma unroll
                for (int k = 0; k < 4; k++) c[i][j][k] = 0.f;

        #pragma unroll
        for (int kb = 0; kb < 4; kb++) {
            load_tile(h,   HID, m0, kc0 + kb * 32, As);
            load_tile(Whh, HID, n0, kc0 + kb * 32, Bs);
            __syncthreads();
            mma_block(c, As, Bs, wm, wn, g, tig);
            __syncthreads();
        }

        #pragma unroll
        for (int mi = 0; mi < 4; mi++) {
            const int lr = wm * 64 + mi * 16 + g;
            #pragma unroll
            for (int ni = 0; ni < 4; ni++) {
                const int lc = wn * 32 + ni * 8 + 2 * tig;
                float2 v0 = make_float2(c[mi][ni][0], c[mi][ni][1]);
                float2 v1 = make_float2(c[mi][ni][2], c[mi][ni][3]);
                *reinterpret_cast<float2*>(myPart + lr * 128 + lc)       = v0;
                *reinterpret_cast<float2*>(myPart + (lr + 8) * 128 + lc) = v1;
            }
        }

        grid_barrier();

        // ---- Phase B: reduce rows [sub*16, sub*16+16) of this tile ----
        {
            float* dst = out + (size_t)t * BATCH * HID;
            const float* base = g_partial + (size_t)(tile * 8) * (128 * 128);
            #pragma unroll
            for (int it = 0; it < 2; it++) {
                const int e   = threadIdx.x + it * 256;  // over 512 float4s
                const int ml  = e >> 5;                  // 0..15
                const int c4  = (e & 31) << 2;           // 0..124
                const int lr  = sub * 16 + ml;           // local row in tile
                const int row = m0 + lr;                 // batch index
                const int col = n0 + c4;

                float4 acc = *reinterpret_cast<const float4*>(dst + (size_t)row * HID + col);
                #pragma unroll
                for (int s = 0; s < 8; s++) {
                    const float4 p = *reinterpret_cast<const float4*>(
                        base + (size_t)s * (128 * 128) + lr * 128 + c4);
                    acc.x += p.x; acc.y += p.y; acc.z += p.z; acc.w += p.w;
                }
                const float4 hv = *reinterpret_cast<const float4*>(h + (size_t)row * HID + col);
                float4 r;
                r.x = 0.9f * hv.x + 0.1f * tanhf(acc.x);
                r.y = 0.9f * hv.y + 0.1f * tanhf(acc.y);
                r.z = 0.9f * hv.z + 0.1f * tanhf(acc.z);
                r.w = 0.9f * hv.w + 0.1f * tanhf(acc.w);
                *reinterpret_cast<float4*>(dst + (size_t)row * HID + col) = r;
                if (write_tail && t == T_STEPS - 1) {
                    *reinterpret_cast<float4*>(
                        out + (size_t)T_STEPS * BATCH * HID + (size_t)row * HID + col) = r;
                }
            }
        }

        grid_barrier();
    }
}

extern "C" void kernel_launch(void* const* d_in, const int* in_sizes, int n_in,
                              void* d_out, int out_size) {
    const float* input = (const float*)d_in[0];  // [512, 256, 256]
    const float* h0    = (const float*)d_in[1];  // [1, 256, 1024]
    const float* Wih   = (const float*)d_in[2];  // [1024, 256]
    const float* Whh   = (const float*)d_in[3];  // [1024, 1024]
    const float* bias  = (const float*)d_in[4];  // [1024]
    float* out = (float*)d_out;

    const int write_tail =
        (out_size >= T_STEPS * BATCH * HID + BATCH * HID) ? 1 : 0;

    // Phase 1: Xpre = input @ Wih^T + bias  -> d_out (reused as preactivation store)
    precompute_kernel<<<dim3(HID / 128, (T_STEPS * BATCH) / 128), 256>>>(input, Wih, bias, out);

    // Phase 2: persistent recurrence over 512 steps
    recurrence_kernel<<<NCTAS, 256>>>(h0, Whh, out, write_tail);
}

// round 2
// speedup vs baseline: 1.1275x; 1.1275x over previous
#include <cuda_runtime.h>
#include <math.h>

#define T_STEPS 512
#define BATCH   256
#define IN_DIM  256
#define HID     1024
#define NCTAS   128
#define SROW    36              // padded smem row (u32): conflict-free, 16B-aligned stride
#define CHUNK   (128 * SROW)    // one 128x32 tf32 tile in smem

// Persistent device state (allowed: __device__ globals, no allocation)
__device__ float    g_partial[NCTAS * 128 * 128];  // 8 MB split-K partials
__device__ unsigned g_h[BATCH * HID];              // tf32 copy of h_t (phase-A operand)
__device__ unsigned g_bar_count;
__device__ unsigned g_bar_phase;

__device__ __forceinline__ unsigned f2tf(float f) {
    unsigned u;
    asm("cvt.rna.tf32.f32 %0, %1;" : "=r"(u) : "f"(f));
    return u;
}

__device__ __forceinline__ void mma8(float c[4], const unsigned a[4], const unsigned b[2]) {
    asm volatile(
        "mma.sync.aligned.m16n8k8.row.col.f32.tf32.tf32.f32 "
        "{%0,%1,%2,%3}, {%4,%5,%6,%7}, {%8,%9}, {%0,%1,%2,%3};\n"
        : "+f"(c[0]), "+f"(c[1]), "+f"(c[2]), "+f"(c[3])
        : "r"(a[0]), "r"(a[1]), "r"(a[2]), "r"(a[3]), "r"(b[0]), "r"(b[1]));
}

// cp.async 16B, L2-only (.cg) — g_h addresses repeat every step; must not hit stale L1.
__device__ __forceinline__ void cp_cg16(unsigned* smem_dst, const unsigned* gmem_src) {
    unsigned s = (unsigned)__cvta_generic_to_shared(smem_dst);
    asm volatile("cp.async.cg.shared.global [%0], [%1], 16;\n" :: "r"(s), "l"(gmem_src));
}
#define CP_COMMIT() asm volatile("cp.async.commit_group;\n")
#define CP_WAIT(n)  asm volatile("cp.async.wait_group %0;\n" :: "n"(n))

__device__ __forceinline__ float tanh_fast(float x) {
    // 1 - 2/(e^{2x}+1): 2 MUFU ops, exact at +/-inf, ~1e-6 rel err
    float e = __expf(2.0f * x);
    return 1.0f - __fdividef(2.0f, e + 1.0f);
}

// fp32 gmem tile (128x32) -> smem tf32, 256 threads. Used for Whh (once) + precompute.
__device__ __forceinline__ void load_tile(const float* __restrict__ g, int ld,
                                          int row0, int col0, unsigned* s) {
    int f = threadIdx.x;
    #pragma unroll
    for (int it = 0; it < 4; it++, f += 256) {
        int r  = f >> 3;
        int c4 = (f & 7) << 2;
        const float4 v = *reinterpret_cast<const float4*>(
            g + (size_t)(row0 + r) * ld + col0 + c4);
        uint4 w;
        w.x = f2tf(v.x); w.y = f2tf(v.y); w.z = f2tf(v.z); w.w = f2tf(v.w);
        *reinterpret_cast<uint4*>(s + r * SROW + c4) = w;
    }
}

// One 32-deep K block of warp MMAs on a 128x128 CTA tile.
__device__ __forceinline__ void mma_block(float c[4][4][4],
                                          const unsigned* As, const unsigned* Bs,
                                          int wm, int wn, int g, int tig) {
    #pragma unroll
    for (int ks = 0; ks < 4; ks++) {
        const int k8 = ks * 8;
        unsigned a[4][4], b[4][2];
        #pragma unroll
        for (int mi = 0; mi < 4; mi++) {
            const unsigned* p = As + (wm * 64 + mi * 16 + g) * SROW + k8 + tig;
            a[mi][0] = p[0];
            a[mi][1] = p[8 * SROW];
            a[mi][2] = p[4];
            a[mi][3] = p[8 * SROW + 4];
        }
        #pragma unroll
        for (int ni = 0; ni < 4; ni++) {
            const unsigned* p = Bs + (wn * 32 + ni * 8 + g) * SROW + k8 + tig;
            b[ni][0] = p[0];
            b[ni][1] = p[4];
        }
        #pragma unroll
        for (int mi = 0; mi < 4; mi++)
            #pragma unroll
            for (int ni = 0; ni < 4; ni++)
                mma8(c[mi][ni], a[mi], b[ni]);
    }
}

// ---------------------------------------------------------------------------
// Kernel 0: g_h = tf32(h0)
// ---------------------------------------------------------------------------
__global__ void init_h_kernel(const float* __restrict__ h0) {
    int i = blockIdx.x * blockDim.x + threadIdx.x;   // over 65536 float4s
    float4 v = reinterpret_cast<const float4*>(h0)[i];
    uint4 w;
    w.x = f2tf(v.x); w.y = f2tf(v.y); w.z = f2tf(v.z); w.w = f2tf(v.w);
    reinterpret_cast<uint4*>(g_h)[i] = w;
}

// ---------------------------------------------------------------------------
// Kernel 1: Xpre = input @ Wih^T + bias -> d_out[t,b,:]
// ---------------------------------------------------------------------------
__global__ void __launch_bounds__(256, 1)
precompute_kernel(const float* __restrict__ input, const float* __restrict__ Wih,
                  const float* __restrict__ bias, float* __restrict__ out) {
    __shared__ unsigned As[CHUNK];
    __shared__ unsigned Bs[CHUNK];

    const int m0 = blockIdx.y * 128;
    const int n0 = blockIdx.x * 128;
    const int warp = threadIdx.x >> 5, lane = threadIdx.x & 31;
    const int wm = warp >> 2, wn = warp & 3, g = lane >> 2, tig = lane & 3;

    float c[4][4][4];
    #pragma unroll
    for (int i = 0; i < 4; i++)
        #pragma unroll
        for (int j = 0; j < 4; j++)
            #pragma unroll
            for (int k = 0; k < 4; k++) c[i][j][k] = 0.f;

    for (int kc = 0; kc < IN_DIM; kc += 32) {
        load_tile(input, IN_DIM, m0, kc, As);
        load_tile(Wih,   IN_DIM, n0, kc, Bs);
        __syncthreads();
        mma_block(c, As, Bs, wm, wn, g, tig);
        __syncthreads();
    }

    #pragma unroll
    for (int mi = 0; mi < 4; mi++) {
        const int row = m0 + wm * 64 + mi * 16 + g;
        #pragma unroll
        for (int ni = 0; ni < 4; ni++) {
            const int col = n0 + wn * 32 + ni * 8 + 2 * tig;
            const float b0 = bias[col], b1 = bias[col + 1];
            float2 v0 = make_float2(c[mi][ni][0] + b0, c[mi][ni][1] + b1);
            float2 v1 = make_float2(c[mi][ni][2] + b0, c[mi][ni][3] + b1);
            *reinterpret_cast<float2*>(out + (size_t)row * HID + col)       = v0;
            *reinterpret_cast<float2*>(out + (size_t)(row + 8) * HID + col) = v1;
        }
    }
}

// ---------------------------------------------------------------------------
// Grid barrier: tight spin (no nanosleep), phase-based (graph-replay safe).
// ---------------------------------------------------------------------------
__device__ __forceinline__ void grid_barrier() {
    __syncthreads();
    if (threadIdx.x == 0) {
        __threadfence();   // release my writes
        const unsigned phase = *(volatile unsigned*)&g_bar_phase;
        if (atomicAdd(&g_bar_count, 1u) == NCTAS - 1) {
            atomicExch(&g_bar_count, 0u);
            __threadfence();
            atomicAdd(&g_bar_phase, 1u);
        } else {
            while (*(volatile unsigned*)&g_bar_phase == phase) { }
        }
        __threadfence();   // acquire others' writes
    }
    __syncthreads();
}

// ---------------------------------------------------------------------------
// Persistent recurrence: 128 CTAs, Whh resident in smem (tf32), h via cp.async.cg
// from g_h (tf32). Split-K 8 partials through gmem, fused reduce+tanh+EMA.
// ---------------------------------------------------------------------------
__global__ void __launch_bounds__(256, 1)
recurrence_kernel(const float* __restrict__ h0, const float* __restrict__ Whh,
                  float* __restrict__ out, int write_tail) {
    extern __shared__ unsigned smem[];
    unsigned* whh  = smem;              // 4 * CHUNK  (resident Whh tile, tf32)
    unsigned* hbuf = smem + 4 * CHUNK;  // 4 * CHUNK  (h tile staging)

    const int cta  = blockIdx.x;       // 0..127
    const int tile = cta >> 3;         // 0..15
    const int sub  = cta & 7;          // 0..7 (K split)
    const int mt   = tile >> 3;
    const int nt   = tile & 7;
    const int m0   = mt * 128;
    const int n0   = nt * 128;
    const int kc0  = sub * 128;

    const int warp = threadIdx.x >> 5, lane = threadIdx.x & 31;
    const int wm = warp >> 2, wn = warp & 3, g = lane >> 2, tig = lane & 3;

    float* myPart = g_partial + (size_t)cta * (128 * 128);

    // One-time: convert this CTA's fixed Whh slice into resident smem (tf32).
    #pragma unroll
    for (int kb = 0; kb < 4; kb++)
        load_tile(Whh, HID, n0, kc0 + kb * 32, whh + kb * CHUNK);
    // (first CP_WAIT+__syncthreads below orders this before use)

    for (int t = 0; t < T_STEPS; t++) {
        // ---- Phase A: issue all 4 h-chunk loads, overlap MMA with tail loads ----
        #pragma unroll
        for (int kb = 0; kb < 4; kb++) {
            unsigned* dstc = hbuf + kb * CHUNK;
            const unsigned* srcb = g_h + (size_t)m0 * HID + kc0 + kb * 32;
            int f = threadIdx.x;
            #pragma unroll
            for (int it = 0; it < 4; it++, f += 256) {
                int r = f >> 3, c4 = (f & 7) << 2;
                cp_cg16(dstc + r * SROW + c4, srcb + (size_t)r * HID + c4);
            }
            CP_COMMIT();
        }

        float c[4][4][4];
        #pragma unroll
        for (int i = 0; i < 4; i++)
            #pragma unroll
            for (int j = 0; j < 4; j++)
                #pragma unroll
                for (int k = 0; k < 4; k++) c[i][j][k] = 0.f;

        CP_WAIT(3); __syncthreads();
        mma_block(c, hbuf + 0 * CHUNK, whh + 0 * CHUNK, wm, wn, g, tig);
        CP_WAIT(2); __syncthreads();
        mma_block(c, hbuf + 1 * CHUNK, whh + 1 * CHUNK, wm, wn, g, tig);
        CP_WAIT(1); __syncthreads();
        mma_block(c, hbuf + 2 * CHUNK, whh + 2 * CHUNK, wm, wn, g, tig);
        CP_WAIT(0); __syncthreads();
        mma_block(c, hbuf + 3 * CHUNK, whh + 3 * CHUNK, wm, wn, g, tig);

        // Store partial tile
        #pragma unroll
        for (int mi = 0; mi < 4; mi++) {
            const int lr = wm * 64 + mi * 16 + g;
            #pragma unroll
            for (int ni = 0; ni < 4; ni++) {
                const int lc = wn * 32 + ni * 8 + 2 * tig;
                float2 v0 = make_float2(c[mi][ni][0], c[mi][ni][1]);
                float2 v1 = make_float2(c[mi][ni][2], c[mi][ni][3]);
                *reinterpret_cast<float2*>(myPart + lr * 128 + lc)       = v0;
                *reinterpret_cast<float2*>(myPart + (lr + 8) * 128 + lc) = v1;
            }
        }

        grid_barrier();

        // ---- Phase B: reduce 8 partials + Xpre -> tanh -> EMA -> out, g_h ----
        {
            const float* h = (t == 0) ? h0 : out + (size_t)(t - 1) * BATCH * HID;
            float* dst = out + (size_t)t * BATCH * HID;
            const float* base = g_partial + (size_t)(tile * 8) * (128 * 128);
            #pragma unroll
            for (int it = 0; it < 2; it++) {
                const int e   = threadIdx.x + it * 256;
                const int ml  = e >> 5;
                const int c4  = (e & 31) << 2;
                const int lr  = sub * 16 + ml;
                const int row = m0 + lr;
                const int col = n0 + c4;

                // .cg loads: these addresses repeat across steps — avoid stale L1.
                float4 acc = __ldcg(reinterpret_cast<const float4*>(
                    dst + (size_t)row * HID + col));
                #pragma unroll
                for (int s = 0; s < 8; s++) {
                    const float4 p = __ldcg(reinterpret_cast<const float4*>(
                        base + (size_t)s * (128 * 128) + lr * 128 + c4));
                    acc.x += p.x; acc.y += p.y; acc.z += p.z; acc.w += p.w;
                }
                const float4 hv = __ldcg(reinterpret_cast<const float4*>(
                    h + (size_t)row * HID + col));
                float4 r;
                r.x = fmaf(0.9f, hv.x, 0.1f * tanh_fast(acc.x));
                r.y = fmaf(0.9f, hv.y, 0.1f * tanh_fast(acc.y));
                r.z = fmaf(0.9f, hv.z, 0.1f * tanh_fast(acc.z));
                r.w = fmaf(0.9f, hv.w, 0.1f * tanh_fast(acc.w));
                *reinterpret_cast<float4*>(dst + (size_t)row * HID + col) = r;
                uint4 w;
                w.x = f2tf(r.x); w.y = f2tf(r.y); w.z = f2tf(r.z); w.w = f2tf(r.w);
                *reinterpret_cast<uint4*>(g_h + (size_t)row * HID + col) = w;
                if (write_tail && t == T_STEPS - 1) {
                    *reinterpret_cast<float4*>(
                        out + (size_t)T_STEPS * BATCH * HID + (size_t)row * HID + col) = r;
                }
            }
        }

        grid_barrier();
    }
}

extern "C" void kernel_launch(void* const* d_in, const int* in_sizes, int n_in,
                              void* d_out, int out_size) {
    const float* input = (const float*)d_in[0];  // [512, 256, 256]
    const float* h0    = (const float*)d_in[1];  // [1, 256, 1024]
    const float* Wih   = (const float*)d_in[2];  // [1024, 256]
    const float* Whh   = (const float*)d_in[3];  // [1024, 1024]
    const float* bias  = (const float*)d_in[4];  // [1024]
    float* out = (float*)d_out;

    const int write_tail =
        (out_size >= T_STEPS * BATCH * HID + BATCH * HID) ? 1 : 0;

    static const int SMEM_BYTES = 8 * CHUNK * 4;  // 147456
    cudaFuncSetAttribute(recurrence_kernel,
                         cudaFuncAttributeMaxDynamicSharedMemorySize, SMEM_BYTES);

    init_h_kernel<<<BATCH * HID / (256 * 4), 256>>>(h0);
    precompute_kernel<<<dim3(HID / 128, (T_STEPS * BATCH) / 128), 256>>>(input, Wih, bias, out);
    recurrence_kernel<<<NCTAS, 256, SMEM_BYTES>>>(h0, Whh, out, write_tail);
}

// round 4
// speedup vs baseline: 1.1366x; 1.0081x over previous
#include <cuda_runtime.h>
#include <math.h>

#define T_STEPS 512
#define BATCH   256
#define IN_DIM  256
#define HID     1024
#define GH      (BATCH * HID)
#define NCTAS   128

#define SROW     40              // padded smem row (u32): conflict-free, LDS.64-friendly
#define HCHUNK   (64 * SROW)     // h chunk: 64 rows x 32 k (permuted)
#define WCHUNK   (128 * SROW)    // Whh chunk: 128 rows x 32 k (permuted)
#define TILEPART (64 * 128)      // one CTA's partial tile

// Persistent device state
__device__ float    g_partial[NCTAS * TILEPART];  // 4 MB split-K partials
__device__ unsigned g_h[GH];                      // tf32 h_t (k-permuted)
__device__ unsigned g_bar_count;
__device__ unsigned g_bar_phase;

__device__ __forceinline__ unsigned f2tf(float f) {
    unsigned u;
    asm("cvt.rna.tf32.f32 %0, %1;" : "=r"(u) : "f"(f));
    return u;
}

__device__ __forceinline__ void mma8(float c[4], const unsigned a[4], const unsigned b[2]) {
    asm volatile(
        "mma.sync.aligned.m16n8k8.row.col.f32.tf32.tf32.f32 "
        "{%0,%1,%2,%3}, {%4,%5,%6,%7}, {%8,%9}, {%0,%1,%2,%3};\n"
        : "+f"(c[0]), "+f"(c[1]), "+f"(c[2]), "+f"(c[3])
        : "r"(a[0]), "r"(a[1]), "r"(a[2]), "r"(a[3]), "r"(b[0]), "r"(b[1]));
}

__device__ __forceinline__ void cp_cg16(unsigned* smem_dst, const unsigned* gmem_src) {
    unsigned s = (unsigned)__cvta_generic_to_shared(smem_dst);
    asm volatile("cp.async.cg.shared.global [%0], [%1], 16;\n" :: "r"(s), "l"(gmem_src));
}
#define CP_COMMIT() asm volatile("cp.async.commit_group;\n")

__device__ __forceinline__ float tanh_fast(float x) {
    float e = __expf(2.0f * x);
    return 1.0f - __fdividef(2.0f, e + 1.0f);
}

// ---------------------------------------------------------------------------
// Kernel 0: g_h = tf32(h0), k-permuted: within each 8-k group, order
// [k0,k4,k1,k5,k2,k6,k3,k7] so mma fragments load as LDS.64.
// ---------------------------------------------------------------------------
__global__ void init_h_kernel(const float* __restrict__ h0) {
    int i = blockIdx.x * blockDim.x + threadIdx.x;   // over 65536 float4
    int row = i >> 8;
    int c0  = (i & 255) * 4;
    const float4 v = *reinterpret_cast<const float4*>(h0 + (size_t)row * HID + c0);
    int base = (c0 & ~7) + ((c0 & 4) ? 1 : 0);
    unsigned* dst = g_h + (size_t)row * HID + base;
    dst[0] = f2tf(v.x); dst[2] = f2tf(v.y); dst[4] = f2tf(v.z); dst[6] = f2tf(v.w);
}

// ---------------------------------------------------------------------------
// Precompute: Xpre = input @ Wih^T + bias -> d_out (register-staged prefetch).
// Non-permuted smem, scalar fragment loads (known-good path).
// ---------------------------------------------------------------------------
__device__ __forceinline__ void fetch_tile(const float* __restrict__ g, int ld,
                                           int row0, int col0, float4* v) {
    int f = threadIdx.x;
    #pragma unroll
    for (int it = 0; it < 4; it++, f += 256) {
        int r = f >> 3, c4 = (f & 7) << 2;
        v[it] = *reinterpret_cast<const float4*>(g + (size_t)(row0 + r) * ld + col0 + c4);
    }
}
__device__ __forceinline__ void store_tile(const float4* v, unsigned* s) {
    int f = threadIdx.x;
    #pragma unroll
    for (int it = 0; it < 4; it++, f += 256) {
        int r = f >> 3, c4 = (f & 7) << 2;
        uint4 w;
        w.x = f2tf(v[it].x); w.y = f2tf(v[it].y); w.z = f2tf(v[it].z); w.w = f2tf(v[it].w);
        *reinterpret_cast<uint4*>(s + r * SROW + c4) = w;
    }
}
__device__ __forceinline__ void mma_block_pre(float c[4][4][4],
                                              const unsigned* As, const unsigned* Bs,
                                              int wm, int wn, int g, int tig) {
    #pragma unroll
    for (int ks = 0; ks < 4; ks++) {
        const int k8 = ks * 8;
        unsigned a[4][4], b[4][2];
        #pragma unroll
        for (int mi = 0; mi < 4; mi++) {
            const unsigned* p = As + (wm * 64 + mi * 16 + g) * SROW + k8 + tig;
            a[mi][0] = p[0]; a[mi][1] = p[8 * SROW]; a[mi][2] = p[4]; a[mi][3] = p[8 * SROW + 4];
        }
        #pragma unroll
        for (int ni = 0; ni < 4; ni++) {
            const unsigned* p = Bs + (wn * 32 + ni * 8 + g) * SROW + k8 + tig;
            b[ni][0] = p[0]; b[ni][1] = p[4];
        }
        #pragma unroll
        for (int mi = 0; mi < 4; mi++)
            #pragma unroll
            for (int ni = 0; ni < 4; ni++)
                mma8(c[mi][ni], a[mi], b[ni]);
    }
}

__global__ void __launch_bounds__(256, 1)
precompute_kernel(const float* __restrict__ input, const float* __restrict__ Wih,
                  const float* __restrict__ bias, float* __restrict__ out) {
    __shared__ unsigned As[128 * SROW];
    __shared__ unsigned Bs[128 * SROW];

    const int m0 = blockIdx.y * 128;
    const int n0 = blockIdx.x * 128;
    const int warp = threadIdx.x >> 5, lane = threadIdx.x & 31;
    const int wm = warp >> 2, wn = warp & 3, g = lane >> 2, tig = lane & 3;

    float c[4][4][4];
    #pragma unroll
    for (int i = 0; i < 4; i++)
        #pragma unroll
        for (int j = 0; j < 4; j++)
            #pragma unroll
            for (int k = 0; k < 4; k++) c[i][j][k] = 0.f;

    float4 pa[4], pb[4];
    fetch_tile(input, IN_DIM, m0, 0, pa);
    fetch_tile(Wih,   IN_DIM, n0, 0, pb);

    for (int kc = 0; kc < IN_DIM; kc += 32) {
        store_tile(pa, As);
        store_tile(pb, Bs);
        __syncthreads();
        if (kc + 32 < IN_DIM) {
            fetch_tile(input, IN_DIM, m0, kc + 32, pa);
            fetch_tile(Wih,   IN_DIM, n0, kc + 32, pb);
        }
        mma_block_pre(c, As, Bs, wm, wn, g, tig);
        __syncthreads();
    }

    #pragma unroll
    for (int mi = 0; mi < 4; mi++) {
        const int row = m0 + wm * 64 + mi * 16 + g;
        #pragma unroll
        for (int ni = 0; ni < 4; ni++) {
            const int col = n0 + wn * 32 + ni * 8 + 2 * tig;
            const float b0 = bias[col], b1 = bias[col + 1];
            float2 v0 = make_float2(c[mi][ni][0] + b0, c[mi][ni][1] + b1);
            float2 v1 = make_float2(c[mi][ni][2] + b0, c[mi][ni][3] + b1);
            *reinterpret_cast<float2*>(out + (size_t)row * HID + col)       = v0;
            *reinterpret_cast<float2*>(out + (size_t)(row + 8) * HID + col) = v1;
        }
    }
}

// ---------------------------------------------------------------------------
// Grid barrier: tight spin, phase-based (graph-replay safe), all-thread fence.
// ---------------------------------------------------------------------------
__device__ __forceinline__ void grid_barrier() {
    __threadfence();   // publish this thread's global writes
    __syncthreads();
    if (threadIdx.x == 0) {
        const unsigned phase = *(volatile unsigned*)&g_bar_phase;
        if (atomicAdd(&g_bar_count, 1u) == NCTAS - 1) {
            atomicExch(&g_bar_count, 0u);
            __threadfence();
            atomicAdd(&g_bar_phase, 1u);
        } else {
            while (*(volatile unsigned*)&g_bar_phase == phase) { }
        }
        __threadfence();   // acquire others' writes
    }
    __syncthreads();
}

// ---------------------------------------------------------------------------
// Recurrence: 128 CTAs = 32 tiles (M64 x N128) x split-K-4, lockstep barriers.
// Whh resident in smem (permuted tf32), h via cp.async.cg ring from g_h.
// ---------------------------------------------------------------------------
__device__ __forceinline__ void issue_h(unsigned* hb, const unsigned* ghsrc, int kb) {
    unsigned* dst = hb + (kb & 3) * HCHUNK;
    const unsigned* src = ghsrc + kb * 32;
    int e = threadIdx.x;
    #pragma unroll
    for (int it = 0; it < 2; it++, e += 256) {
        int r = e >> 3, g4 = (e & 7) * 4;
        cp_cg16(dst + r * SROW + g4, src + (size_t)r * HID + g4);
    }
}

__device__ __forceinline__ void mma_chunk(float c[2][4][4],
                                          const unsigned* As, const unsigned* Bs,
                                          int wm, int wn, int g, int tig) {
    #pragma unroll
    for (int ks = 0; ks < 4; ks++) {
        const int ko = ks * 8 + 2 * tig;   // permuted: (k_tig, k_tig+4) adjacent
        uint2 alo[2], ahi[2], bb[4];
        #pragma unroll
        for (int mi = 0; mi < 2; mi++) {
            const unsigned* p = As + (wm * 32 + mi * 16 + g) * SROW + ko;
            alo[mi] = *reinterpret_cast<const uint2*>(p);
            ahi[mi] = *reinterpret_cast<const uint2*>(p + 8 * SROW);
        }
        #pragma unroll
        for (int ni = 0; ni < 4; ni++)
            bb[ni] = *reinterpret_cast<const uint2*>(Bs + (wn * 32 + ni * 8 + g) * SROW + ko);
        #pragma unroll
        for (int mi = 0; mi < 2; mi++) {
            unsigned a[4] = {alo[mi].x, ahi[mi].x, alo[mi].y, ahi[mi].y};
            #pragma unroll
            for (int ni = 0; ni < 4; ni++) {
                unsigned b2[2] = {bb[ni].x, bb[ni].y};
                mma8(c[mi][ni], a, b2);
            }
        }
    }
}

__global__ void __launch_bounds__(256, 1)
recurrence_kernel(const float* __restrict__ h0, const float* __restrict__ Whh,
                  float* __restrict__ out, int write_tail) {
    extern __shared__ unsigned smem[];
    unsigned* whh  = smem;                // 8 * WCHUNK (resident, permuted tf32)
    unsigned* hbuf = smem + 8 * WCHUNK;   // 4 * HCHUNK ring

    const int cta  = blockIdx.x;          // 0..127
    const int tile = cta >> 2;            // 0..31
    const int sub  = cta & 3;             // K-split
    const int mt   = tile >> 3;           // 0..3   (64-row batch block)
    const int nt   = tile & 7;            // 0..7   (128-col hidden block)
    const int m0   = mt * 64;
    const int n0   = nt * 128;
    const int kc0  = sub * 256;

    const int warp = threadIdx.x >> 5, lane = threadIdx.x & 31;
    const int wm = warp >> 2, wn = warp & 3, g = lane >> 2, tig = lane & 3;

    // One-time: resident Whh slice [n0..n0+128) x [kc0..kc0+256) -> permuted tf32
    #pragma unroll
    for (int kb = 0; kb < 8; kb++) {
        unsigned* ws = whh + kb * WCHUNK;
        int e = threadIdx.x;
        #pragma unroll
        for (int it = 0; it < 4; it++, e += 256) {
            int r = e >> 3, c4 = (e & 7) * 4;
            const float4 v = *reinterpret_cast<const float4*>(
                Whh + (size_t)(n0 + r) * HID + kc0 + kb * 32 + c4);
            int base = (c4 & ~7) + ((c4 & 4) ? 1 : 0);
            ws[r * SROW + base + 0] = f2tf(v.x);
            ws[r * SROW + base + 2] = f2tf(v.y);
            ws[r * SROW + base + 4] = f2tf(v.z);
            ws[r * SROW + base + 6] = f2tf(v.w);
        }
    }

    // Phase-B partition is CTA-stationary: keep h (fp32) in registers.
    int rowv[2], colv[2];
    float4 hreg[2];
    {
        int e = threadIdx.x;
        #pragma unroll
        for (int it = 0; it < 2; it++, e += 256) {
            int ml = e >> 5, c4 = (e & 31) * 4;
            rowv[it] = m0 + sub * 16 + ml;
            colv[it] = n0 + c4;
            hreg[it] = *reinterpret_cast<const float4*>(h0 + (size_t)rowv[it] * HID + colv[it]);
        }
    }

    const unsigned* ghsrc = g_h + (size_t)m0 * HID + kc0;
    float* myPart = g_partial + (size_t)cta * TILEPART;

    for (int t = 0; t < T_STEPS; t++) {
        // ---- Phase A: pipelined split-K GEMM over kc0..kc0+256 ----
        issue_h(hbuf, ghsrc, 0); CP_COMMIT();
        issue_h(hbuf, ghsrc, 1); CP_COMMIT();
        issue_h(hbuf, ghsrc, 2); CP_COMMIT();

        float c[2][4][4];
        #pragma unroll
        for (int i = 0; i < 2; i++)
            #pragma unroll
            for (int j = 0; j < 4; j++)
                #pragma unroll
                for (int k = 0; k < 4; k++) c[i][j][k] = 0.f;

#define STEP_KB(KB, WN)                                                      \
        asm volatile("cp.async.wait_group %0;\n" :: "n"(WN));                \
        __syncthreads();                                                     \
        if ((KB) + 3 < 8) { issue_h(hbuf, ghsrc, (KB) + 3); CP_COMMIT(); }   \
        mma_chunk(c, hbuf + ((KB) & 3) * HCHUNK, whh + (KB) * WCHUNK, wm, wn, g, tig);

        STEP_KB(0, 2) STEP_KB(1, 2) STEP_KB(2, 2) STEP_KB(3, 2)
        STEP_KB(4, 2) STEP_KB(5, 2) STEP_KB(6, 1) STEP_KB(7, 0)
#undef STEP_KB

        // store partial tile
        #pragma unroll
        for (int mi = 0; mi < 2; mi++) {
            const int lr = wm * 32 + mi * 16 + g;
            #pragma unroll
            for (int ni = 0; ni < 4; ni++) {
                const int lc = wn * 32 + ni * 8 + 2 * tig;
                *reinterpret_cast<float2*>(myPart + lr * 128 + lc) =
                    make_float2(c[mi][ni][0], c[mi][ni][1]);
                *reinterpret_cast<float2*>(myPart + (lr + 8) * 128 + lc) =
                    make_float2(c[mi][ni][2], c[mi][ni][3]);
            }
        }

        grid_barrier();

        // ---- Phase B: reduce 4 partials + Xpre -> tanh -> EMA -> out, g_h ----
        {
            float* dst = out + (size_t)t * GH;
            const float* pb = g_partial + (size_t)(tile * 4) * TILEPART;
            int e = threadIdx.x;
            #pragma unroll
            for (int it = 0; it < 2; it++, e += 256) {
                const int ml = e >> 5, c4 = (e & 31) * 4;
                const int lr = sub * 16 + ml;
                const int row = rowv[it], col = colv[it];

                float4 acc = *reinterpret_cast<const float4*>(dst + (size_t)row * HID + col);
                #pragma unroll
                for (int s = 0; s < 4; s++) {
                    const float4 p = __ldcg(reinterpret_cast<const float4*>(
                        pb + (size_t)s * TILEPART + lr * 128 + c4));
                    acc.x += p.x; acc.y += p.y; acc.z += p.z; acc.w += p.w;
                }
                float4 r;
                r.x = fmaf(0.9f, hreg[it].x, 0.1f * tanh_fast(acc.x));
                r.y = fmaf(0.9f, hreg[it].y, 0.1f * tanh_fast(acc.y));
                r.z = fmaf(0.9f, hreg[it].z, 0.1f * tanh_fast(acc.z));
                r.w = fmaf(0.9f, hreg[it].w, 0.1f * tanh_fast(acc.w));
                hreg[it] = r;
                *reinterpret_cast<float4*>(dst + (size_t)row * HID + col) = r;

                const int base = (col & ~7) + ((col & 4) ? 1 : 0);
                unsigned* gp = g_h + (size_t)row * HID + base;
                gp[0] = f2tf(r.x); gp[2] = f2tf(r.y); gp[4] = f2tf(r.z); gp[6] = f2tf(r.w);

                if (write_tail && t == T_STEPS - 1) {
                    *reinterpret_cast<float4*>(
                        out + (size_t)T_STEPS * GH + (size_t)row * HID + col) = r;
                }
            }
        }

        grid_barrier();
    }
}

extern "C" void kernel_launch(void* const* d_in, const int* in_sizes, int n_in,
                              void* d_out, int out_size) {
    const float* input = (const float*)d_in[0];  // [512, 256, 256]
    const float* h0    = (const float*)d_in[1];  // [1, 256, 1024]
    const float* Wih   = (const float*)d_in[2];  // [1024, 256]
    const float* Whh   = (const float*)d_in[3];  // [1024, 1024]
    const float* bias  = (const float*)d_in[4];  // [1024]
    float* out = (float*)d_out;

    const int write_tail = (out_size >= T_STEPS * GH + GH) ? 1 : 0;

    static const int SMEM_BYTES = (8 * WCHUNK + 4 * HCHUNK) * 4;  // 204800
    cudaFuncSetAttribute(recurrence_kernel,
                         cudaFuncAttributeMaxDynamicSharedMemorySize, SMEM_BYTES);

    init_h_kernel<<<GH / 4 / 256, 256>>>(h0);
    precompute_kernel<<<dim3(HID / 128, (T_STEPS * BATCH) / 128), 256>>>(input, Wih, bias, out);
    recurrence_kernel<<<NCTAS, 256, SMEM_BYTES>>>(h0, Whh, out, write_tail);
}